// round 17
// baseline (speedup 1.0000x reference)
#include <cuda_runtime.h>

// y[b, i] = input[b, i] * diag(weight)[i] + bias[i]
// B = 8192, N = 4096, fp32.
//
// FINAL (converged) kernel — measured 47.104us floor (R8, tied by R3/R14).
// Kernel 1: gather diag(weight) -> __device__ scratch (tiny).
// Kernel 2: wide-stride float4 streamer, MLP=4, exact-fit grid:
//   16384 CTAs x 256 threads, 4 float4 per thread at idx + k*gridstride,
//   no bounds checks/tail. 256 MB mandatory traffic at the chip's warm
//   mixed L2/DRAM ceiling (~6.9 TB/s effective); remaining ~10.1us of the
//   timed total is fixed harness/replay cost (invariant to kernel count).

#define N_COLS 4096
#define N4 (N_COLS / 4)          // 1024 float4 columns
#define THREADS 256
#define UNROLL 4

__device__ float g_diag[N_COLS];

__global__ void extract_diag_kernel(const float* __restrict__ weight, int n) {
    int i = blockIdx.x * blockDim.x + threadIdx.x;
    if (i < n) {
        g_diag[i] = weight[(size_t)i * (size_t)(n + 1)];
    }
}

__global__ void __launch_bounds__(THREADS)
scale_bias_kernel(const float4* __restrict__ in,
                  const float4* __restrict__ bias4,
                  float4* __restrict__ out) {
    const float4* __restrict__ d4 = reinterpret_cast<const float4*>(g_diag);

    int idx0   = blockIdx.x * THREADS + threadIdx.x;
    int stride = gridDim.x * THREADS;      // grid covers total4/UNROLL exactly

    // Front-batched independent loads (MLP = 4), default caching.
    float4 x[UNROLL];
    #pragma unroll
    for (int k = 0; k < UNROLL; k++) {
        x[k] = in[idx0 + k * stride];
    }

    #pragma unroll
    for (int k = 0; k < UNROLL; k++) {
        int idx = idx0 + k * stride;
        int c = idx & (N4 - 1);            // column (N4 power of two)
        float4 d = d4[c];                  // 16 KB table, L1-resident
        float4 b = bias4[c];               // 16 KB table, L1-resident
        float4 y;
        y.x = fmaf(x[k].x, d.x, b.x);
        y.y = fmaf(x[k].y, d.y, b.y);
        y.z = fmaf(x[k].z, d.z, b.z);
        y.w = fmaf(x[k].w, d.w, b.w);
        out[idx] = y;
    }
}

extern "C" void kernel_launch(void* const* d_in, const int* in_sizes, int n_in,
                              void* d_out, int out_size) {
    const float* input  = (const float*)d_in[0];   // [B, N]
    const float* weight = (const float*)d_in[1];   // [N, N]
    const float* bias   = (const float*)d_in[2];   // [N]
    float* out = (float*)d_out;

    // 1) gather diagonal
    extract_diag_kernel<<<(N_COLS + 255) / 256, 256>>>(weight, N_COLS);

    // 2) wide-stride streamer: total4 = B*N/4 = 2^23, divides exactly.
    int total4 = out_size / 4;
    int blocks = total4 / (THREADS * UNROLL);      // 16384
    scale_bias_kernel<<<blocks, THREADS>>>(
        reinterpret_cast<const float4*>(input),
        reinterpret_cast<const float4*>(bias),
        reinterpret_cast<float4*>(out));
}